// round 3
// baseline (speedup 1.0000x reference)
#include <cuda_runtime.h>
#include <cstdint>

constexpr int N_NODES = 100000;
constexpr int N_EDGES = 3200000;
constexpr int IN_CH   = 128;
constexpr int HID     = 16;
constexpr int OUT_CH  = 64;

// ---------------- scratch (device globals; allocation-free) ----------------
__device__ __align__(16) int   g_deg [N_NODES];
__device__ __align__(16) float g_dinv[N_NODES];
__device__ __align__(16) int   g_src [N_EDGES];
__device__ __align__(16) int   g_dst [N_EDGES];
__device__ __align__(16) float g_h1  [N_NODES * HID];   // x @ W1
__device__ __align__(16) float g_acc1[N_NODES * HID];   // scattered layer-1 pre-activation
__device__ __align__(16) float g_g   [N_NODES * HID];   // relu(acc1 + b1)
__device__ __align__(16) float g_acc2[N_NODES * HID];   // scattered layer-2 (16-dim, pre-W2)
__device__ int g_is32;                                  // edge-index dtype flag

// ---------------- kernels ----------------

__global__ void k_init_deg() {
    int i = blockIdx.x * blockDim.x + threadIdx.x;
    if (i < N_NODES) g_deg[i] = 1;   // self-loop
    if (i == 0) g_is32 = 0;
}

// Detect whether the edge-index buffer is really int64 or silently int32
// (JAX without x64 produces int32 despite dtype=jnp.int64). If any of the
// first 256 values, read as int64, is out of [0, N_NODES), it must be int32.
__global__ void k_detect_fmt(const long long* __restrict__ ei) {
    int t = threadIdx.x;                   // one block, 256 threads
    long long v = ei[t];
    if (v < 0 || v >= (long long)N_NODES) g_is32 = 1;
}

__global__ void k_prep_edges(const void* __restrict__ eiv) {
    int e = blockIdx.x * blockDim.x + threadIdx.x;
    if (e >= N_EDGES) return;
    int s, d;
    if (g_is32) {
        const int* e32 = (const int*)eiv;
        s = e32[e];
        d = e32[N_EDGES + e];
    } else {
        const long long* e64 = (const long long*)eiv;
        s = (int)e64[e];
        d = (int)e64[N_EDGES + e];
    }
    // clamp: turn any residual dtype misread into a wrong answer (diagnosable
    // rel_err) rather than an illegal memory access
    s = min(max(s, 0), N_NODES - 1);
    d = min(max(d, 0), N_NODES - 1);
    g_src[e] = s;
    g_dst[e] = d;
    atomicAdd(&g_deg[d], 1);
}

__global__ void k_dinv() {
    int i = blockIdx.x * blockDim.x + threadIdx.x;
    if (i < N_NODES) g_dinv[i] = rsqrtf((float)g_deg[i]);
}

// h1 = x @ W1 ; acc1 = h1 * dinv^2 (self-loop contribution)
__global__ void k_gemm1(const float* __restrict__ x, const float* __restrict__ W1) {
    __shared__ float sW[IN_CH * HID];   // 8 KB
    for (int t = threadIdx.x; t < IN_CH * HID; t += blockDim.x) sW[t] = W1[t];
    __syncthreads();

    int row = blockIdx.x * blockDim.x + threadIdx.x;
    if (row >= N_NODES) return;

    float acc[HID];
#pragma unroll
    for (int j = 0; j < HID; j++) acc[j] = 0.f;

    const float4* xr = reinterpret_cast<const float4*>(x + (size_t)row * IN_CH);
#pragma unroll 4
    for (int k4 = 0; k4 < IN_CH / 4; k4++) {
        float4 v = xr[k4];
        const float* w = &sW[k4 * 4 * HID];
#pragma unroll
        for (int j = 0; j < HID; j++)
            acc[j] += v.x * w[j] + v.y * w[HID + j] + v.z * w[2 * HID + j] + v.w * w[3 * HID + j];
    }

    float dv  = g_dinv[row];
    float dv2 = dv * dv;
    float4* h = reinterpret_cast<float4*>(g_h1  + (size_t)row * HID);
    float4* a = reinterpret_cast<float4*>(g_acc1 + (size_t)row * HID);
#pragma unroll
    for (int q = 0; q < HID / 4; q++) {
        float4 hv = make_float4(acc[4 * q + 0], acc[4 * q + 1], acc[4 * q + 2], acc[4 * q + 3]);
        h[q] = hv;
        a[q] = make_float4(hv.x * dv2, hv.y * dv2, hv.z * dv2, hv.w * dv2);
    }
}

__device__ __forceinline__ void red4(float* addr, float a, float b, float c, float d) {
    asm volatile("red.global.add.v4.f32 [%0], {%1, %2, %3, %4};"
                 :: "l"(addr), "f"(a), "f"(b), "f"(c), "f"(d) : "memory");
}

// layer==0: gather g_h1 -> acc1 ; layer==1: gather g_g -> acc2
__global__ void k_scatter(int layer) {
    int e = blockIdx.x * blockDim.x + threadIdx.x;
    if (e >= N_EDGES) return;
    int s = g_src[e];
    int d = g_dst[e];
    float w = g_dinv[s] * g_dinv[d];

    const float* hbase = (layer == 0) ? g_h1 : g_g;
    float*       abase = (layer == 0) ? g_acc1 : g_acc2;

    const float4* hs = reinterpret_cast<const float4*>(hbase + (size_t)s * HID);
    float*        ad = abase + (size_t)d * HID;
#pragma unroll
    for (int q = 0; q < HID / 4; q++) {
        float4 v = hs[q];
        red4(ad + 4 * q, v.x * w, v.y * w, v.z * w, v.w * w);
    }
}

// g = relu(acc1 + b1) ; acc2 = g * dinv^2 (self-loop contribution for layer 2)
__global__ void k_relu_init2(const float* __restrict__ b1) {
    int i = blockIdx.x * blockDim.x + threadIdx.x;         // over N*HID/4 float4s
    if (i >= N_NODES * HID / 4) return;
    int row = i / (HID / 4);
    int q   = i % (HID / 4);

    float4 a  = reinterpret_cast<const float4*>(g_acc1)[i];
    float4 bb = reinterpret_cast<const float4*>(b1)[q];
    float4 gv;
    gv.x = fmaxf(a.x + bb.x, 0.f);
    gv.y = fmaxf(a.y + bb.y, 0.f);
    gv.z = fmaxf(a.z + bb.z, 0.f);
    gv.w = fmaxf(a.w + bb.w, 0.f);
    reinterpret_cast<float4*>(g_g)[i] = gv;

    float dv  = g_dinv[row];
    float dv2 = dv * dv;
    reinterpret_cast<float4*>(g_acc2)[i] =
        make_float4(gv.x * dv2, gv.y * dv2, gv.z * dv2, gv.w * dv2);
}

// out = acc2 @ W2 + b2   (100000x16 @ 16x64)
__global__ void k_gemm2(const float* __restrict__ W2, const float* __restrict__ b2,
                        float* __restrict__ out) {
    __shared__ float sW[HID * OUT_CH];   // 4 KB
    __shared__ float srow[4][HID];
    for (int t = threadIdx.x; t < HID * OUT_CH; t += blockDim.x) sW[t] = W2[t];

    int tid = threadIdx.x;                 // blockDim = 256 = 4 rows x 64 cols
    int r   = tid / OUT_CH;                // 0..3
    int j   = tid % OUT_CH;                // 0..63
    int row = blockIdx.x * 4 + r;

    if (tid < 4 * HID) {
        int rr = tid / HID, kk = tid % HID;
        int grow = blockIdx.x * 4 + rr;
        srow[rr][kk] = (grow < N_NODES) ? g_acc2[(size_t)grow * HID + kk] : 0.f;
    }
    __syncthreads();

    if (row >= N_NODES) return;
    float s = b2[j];
#pragma unroll
    for (int k = 0; k < HID; k++) s += srow[r][k] * sW[k * OUT_CH + j];
    out[(size_t)row * OUT_CH + j] = s;
}

// ---------------- launch ----------------
extern "C" void kernel_launch(void* const* d_in, const int* in_sizes, int n_in,
                              void* d_out, int out_size) {
    const float*     x  = (const float*)d_in[0];
    const void*      ei = (const void*)d_in[1];
    const float*     W1 = (const float*)d_in[2];
    const float*     b1 = (const float*)d_in[3];
    const float*     W2 = (const float*)d_in[4];
    const float*     b2 = (const float*)d_in[5];
    float*           out = (float*)d_out;

    const int TB = 256;
    k_init_deg<<<(N_NODES + TB - 1) / TB, TB>>>();
    k_detect_fmt<<<1, 256>>>((const long long*)ei);
    k_prep_edges<<<(N_EDGES + TB - 1) / TB, TB>>>(ei);
    k_dinv<<<(N_NODES + TB - 1) / TB, TB>>>();

    k_gemm1<<<(N_NODES + 127) / 128, 128>>>(x, W1);
    k_scatter<<<(N_EDGES + TB - 1) / TB, TB>>>(0);
    k_relu_init2<<<(N_NODES * HID / 4 + TB - 1) / TB, TB>>>(b1);
    k_scatter<<<(N_EDGES + TB - 1) / TB, TB>>>(1);
    k_gemm2<<<(N_NODES + 3) / 4, TB>>>(W2, b2, out);
}

// round 4
// speedup vs baseline: 1.8456x; 1.8456x over previous
#include <cuda_runtime.h>
#include <cstdint>

constexpr int N_NODES = 100000;
constexpr int N_EDGES = 3200000;
constexpr int IN_CH   = 128;
constexpr int HID     = 16;
constexpr int OUT_CH  = 64;
constexpr int SCAN_BLK = 256;
constexpr int N_BLK1   = (N_NODES + SCAN_BLK - 1) / SCAN_BLK;   // 391

// ---------------- scratch (device globals; allocation-free) ----------------
__device__ __align__(16) int   g_deg   [N_NODES];
__device__ __align__(16) float g_dinv  [N_NODES];
__device__ __align__(16) int   g_off   [N_NODES + 1];
__device__ __align__(16) int   g_cursor[N_NODES];
__device__ __align__(16) int   g_bsum  [N_BLK1];
__device__ __align__(16) int   g_csr   [N_EDGES];               // src per in-edge, grouped by dst
__device__ __align__(16) float g_h1s   [N_NODES * HID];         // (x@W1) * dinv[row]
__device__ __align__(16) float g_gs    [N_NODES * HID];         // relu(...) * dinv[row]
__device__ int g_is32;

// ---------------- helpers ----------------
__device__ __forceinline__ int2 load_edge(const void* eiv, int e, int is32) {
    int s, d;
    if (is32) {
        const int* p = (const int*)eiv;
        s = p[e]; d = p[N_EDGES + e];
    } else {
        const long long* p = (const long long*)eiv;
        s = (int)p[e]; d = (int)p[N_EDGES + e];
    }
    s = min(max(s, 0), N_NODES - 1);
    d = min(max(d, 0), N_NODES - 1);
    return make_int2(s, d);
}

// ---------------- prep ----------------
__global__ void k_init() {
    int i = blockIdx.x * blockDim.x + threadIdx.x;
    if (i < N_NODES) g_deg[i] = 0;
    if (i == 0) g_is32 = 0;
}

// JAX without x64 silently yields int32 despite the int64 annotation.
__global__ void k_detect_fmt(const long long* __restrict__ ei) {
    long long v = ei[threadIdx.x];
    if (v < 0 || v >= (long long)N_NODES) g_is32 = 1;
}

__global__ void k_count(const void* __restrict__ eiv) {
    int e = blockIdx.x * blockDim.x + threadIdx.x;
    if (e >= N_EDGES) return;
    int d;
    if (g_is32) d = ((const int*)eiv)[N_EDGES + e];
    else        d = (int)((const long long*)eiv)[N_EDGES + e];
    d = min(max(d, 0), N_NODES - 1);
    atomicAdd(&g_deg[d], 1);
}

__global__ void k_dinv() {
    int i = blockIdx.x * blockDim.x + threadIdx.x;
    if (i < N_NODES) g_dinv[i] = rsqrtf((float)(g_deg[i] + 1));   // +1 self-loop
}

// exclusive scan of g_deg -> g_off (3-kernel two-level scan)
__global__ void k_scan1() {
    __shared__ int s[SCAN_BLK];
    int i = blockIdx.x * SCAN_BLK + threadIdx.x;
    int v = (i < N_NODES) ? g_deg[i] : 0;
    s[threadIdx.x] = v;
    __syncthreads();
    for (int o = 1; o < SCAN_BLK; o <<= 1) {
        int t = (threadIdx.x >= o) ? s[threadIdx.x - o] : 0;
        __syncthreads();
        s[threadIdx.x] += t;
        __syncthreads();
    }
    if (i < N_NODES) g_off[i] = s[threadIdx.x] - v;               // exclusive
    if (threadIdx.x == SCAN_BLK - 1) g_bsum[blockIdx.x] = s[threadIdx.x];
}

__global__ void k_scan2() {     // 1 block, 512 threads; scan 391 block sums
    __shared__ int s[512];
    int v = (threadIdx.x < N_BLK1) ? g_bsum[threadIdx.x] : 0;
    s[threadIdx.x] = v;
    __syncthreads();
    for (int o = 1; o < 512; o <<= 1) {
        int t = (threadIdx.x >= o) ? s[threadIdx.x - o] : 0;
        __syncthreads();
        s[threadIdx.x] += t;
        __syncthreads();
    }
    if (threadIdx.x < N_BLK1) g_bsum[threadIdx.x] = s[threadIdx.x] - v;  // exclusive
}

__global__ void k_scan3() {
    int i = blockIdx.x * blockDim.x + threadIdx.x;
    if (i < N_NODES) {
        int o = g_off[i] + g_bsum[i / SCAN_BLK];
        g_off[i] = o;
        g_cursor[i] = o;
    }
    if (i == 0) g_off[N_NODES] = N_EDGES;
}

__global__ void k_fill(const void* __restrict__ eiv) {
    int e = blockIdx.x * blockDim.x + threadIdx.x;
    if (e >= N_EDGES) return;
    int2 sd = load_edge(eiv, e, g_is32);
    int pos = atomicAdd(&g_cursor[sd.y], 1);
    g_csr[pos] = sd.x;
}

// ---------------- layer 1 GEMM: h1s = (x @ W1) * dinv[row] ----------------
__global__ void k_gemm1(const float* __restrict__ x, const float* __restrict__ W1) {
    __shared__ float sW[IN_CH * HID];   // 8 KB
    for (int t = threadIdx.x; t < IN_CH * HID; t += blockDim.x) sW[t] = W1[t];
    __syncthreads();

    int row = blockIdx.x * blockDim.x + threadIdx.x;
    if (row >= N_NODES) return;

    float acc[HID];
#pragma unroll
    for (int j = 0; j < HID; j++) acc[j] = 0.f;

    const float4* xr = reinterpret_cast<const float4*>(x + (size_t)row * IN_CH);
#pragma unroll 4
    for (int k4 = 0; k4 < IN_CH / 4; k4++) {
        float4 v = xr[k4];
        const float* w = &sW[k4 * 4 * HID];
#pragma unroll
        for (int j = 0; j < HID; j++)
            acc[j] += v.x * w[j] + v.y * w[HID + j] + v.z * w[2 * HID + j] + v.w * w[3 * HID + j];
    }

    float dv = g_dinv[row];
    float4* h = reinterpret_cast<float4*>(g_h1s + (size_t)row * HID);
#pragma unroll
    for (int q = 0; q < HID / 4; q++)
        h[q] = make_float4(acc[4 * q + 0] * dv, acc[4 * q + 1] * dv,
                           acc[4 * q + 2] * dv, acc[4 * q + 3] * dv);
}

// ---------------- gather layer 1 (fused bias+relu+rescale) ----------------
// warp per node; 8 groups of 4 lanes; group handles one in-edge per iter.
__global__ void k_gather1(const float* __restrict__ b1) {
    int nid = (blockIdx.x * blockDim.x + threadIdx.x) >> 5;
    if (nid >= N_NODES) return;
    int lane = threadIdx.x & 31;
    int grp = lane >> 2, q = lane & 3;

    int beg = g_off[nid], end = g_off[nid + 1];
    const float4* H = reinterpret_cast<const float4*>(g_h1s);

    float4 acc = (grp == 0) ? H[nid * 4 + q] : make_float4(0.f, 0.f, 0.f, 0.f); // self-loop
    for (int i = beg + grp; i < end; i += 8) {
        int s = g_csr[i];
        float4 v = H[s * 4 + q];
        acc.x += v.x; acc.y += v.y; acc.z += v.z; acc.w += v.w;
    }
#pragma unroll
    for (int m = 16; m >= 4; m >>= 1) {
        acc.x += __shfl_xor_sync(0xffffffffu, acc.x, m);
        acc.y += __shfl_xor_sync(0xffffffffu, acc.y, m);
        acc.z += __shfl_xor_sync(0xffffffffu, acc.z, m);
        acc.w += __shfl_xor_sync(0xffffffffu, acc.w, m);
    }
    if (grp == 0) {
        float dv = g_dinv[nid];
        float4 bb = reinterpret_cast<const float4*>(b1)[q];
        float4 r;
        r.x = fmaxf(acc.x * dv + bb.x, 0.f) * dv;
        r.y = fmaxf(acc.y * dv + bb.y, 0.f) * dv;
        r.z = fmaxf(acc.z * dv + bb.z, 0.f) * dv;
        r.w = fmaxf(acc.w * dv + bb.w, 0.f) * dv;
        reinterpret_cast<float4*>(g_gs)[nid * 4 + q] = r;
    }
}

// ---------------- gather layer 2 fused with GEMM2 (+b2) ----------------
// block = 256 = 8 warps, warp per node. W2 staged in shared.
__global__ void k_gather2_gemm2(const float* __restrict__ W2,
                                const float* __restrict__ b2,
                                float* __restrict__ out) {
    __shared__ float sW[HID * OUT_CH];                 // 4 KB
    __shared__ __align__(16) float s_a[8][HID];
    for (int t = threadIdx.x; t < HID * OUT_CH; t += blockDim.x) sW[t] = W2[t];
    __syncthreads();

    int w = threadIdx.x >> 5;
    int nid = blockIdx.x * 8 + w;
    if (nid >= N_NODES) return;
    int lane = threadIdx.x & 31;
    int grp = lane >> 2, q = lane & 3;

    int beg = g_off[nid], end = g_off[nid + 1];
    const float4* G = reinterpret_cast<const float4*>(g_gs);

    float4 acc = (grp == 0) ? G[nid * 4 + q] : make_float4(0.f, 0.f, 0.f, 0.f); // self-loop
    for (int i = beg + grp; i < end; i += 8) {
        int s = g_csr[i];
        float4 v = G[s * 4 + q];
        acc.x += v.x; acc.y += v.y; acc.z += v.z; acc.w += v.w;
    }
#pragma unroll
    for (int m = 16; m >= 4; m >>= 1) {
        acc.x += __shfl_xor_sync(0xffffffffu, acc.x, m);
        acc.y += __shfl_xor_sync(0xffffffffu, acc.y, m);
        acc.z += __shfl_xor_sync(0xffffffffu, acc.z, m);
        acc.w += __shfl_xor_sync(0xffffffffu, acc.w, m);
    }
    if (grp == 0) {
        float dv = g_dinv[nid];
        reinterpret_cast<float4*>(&s_a[w][q * 4])[0] =
            make_float4(acc.x * dv, acc.y * dv, acc.z * dv, acc.w * dv);
    }
    __syncwarp();

    // each lane computes cols {lane, lane+32}
    float a0 = b2[lane], a1 = b2[lane + 32];
#pragma unroll
    for (int k = 0; k < HID; k++) {
        float av = s_a[w][k];
        a0 += av * sW[k * OUT_CH + lane];
        a1 += av * sW[k * OUT_CH + lane + 32];
    }
    out[(size_t)nid * OUT_CH + lane]      = a0;
    out[(size_t)nid * OUT_CH + lane + 32] = a1;
}

// ---------------- launch ----------------
extern "C" void kernel_launch(void* const* d_in, const int* in_sizes, int n_in,
                              void* d_out, int out_size) {
    const float* x  = (const float*)d_in[0];
    const void*  ei = (const void*)d_in[1];
    const float* W1 = (const float*)d_in[2];
    const float* b1 = (const float*)d_in[3];
    const float* W2 = (const float*)d_in[4];
    const float* b2 = (const float*)d_in[5];
    float*       out = (float*)d_out;

    const int TB = 256;
    k_init<<<(N_NODES + TB - 1) / TB, TB>>>();
    k_detect_fmt<<<1, 256>>>((const long long*)ei);
    k_count<<<(N_EDGES + TB - 1) / TB, TB>>>(ei);
    k_dinv<<<(N_NODES + TB - 1) / TB, TB>>>();
    k_scan1<<<N_BLK1, SCAN_BLK>>>();
    k_scan2<<<1, 512>>>();
    k_scan3<<<(N_NODES + TB - 1) / TB, TB>>>();
    k_fill<<<(N_EDGES + TB - 1) / TB, TB>>>(ei);

    k_gemm1<<<(N_NODES + 127) / 128, 128>>>(x, W1);
    k_gather1<<<(N_NODES * 32 + TB - 1) / TB, TB>>>(b1);
    k_gather2_gemm2<<<(N_NODES + 7) / 8, TB>>>(W2, b2, out);
}